// round 11
// baseline (speedup 1.0000x reference)
#include <cuda_runtime.h>
#include <cuda_bf16.h>
#include <math.h>
#include <stdint.h>

#define Nn 8192
#define Ee 131072
#define Hh 128
#define NEGV (-1e30f)
#define NSLAB 8
#define NCAND 4
#define PAD 132
#define SMEM_GEMM (2*128*PAD*4)          // scalar GEMMs: As + Bs
#define RS 392                            // bf16 row stride for MMA tiles (784 B)
#define KS_N 24                           // 384 / 16 k-steps
#define SMEM_MMA (2*128*RS*2)             // 200704 B: A tile + B tile (bf16)

// ---------------- device scratch ----------------
__device__ __align__(16) float g_deg[Nn];
__device__ __align__(16) float g_rsq[Nn];
__device__ __align__(16) float g_xw[Nn*Hh];
__device__ __align__(16) float g_agg[Nn*Hh];
__device__ __align__(16) float g_h[Nn*Hh];
__device__ __align__(16) float g_t[Nn*Hh];
__device__ __align__(16) float g_Ht[Nn*Hh];
__device__ __align__(16) float g_Hs[Nn*Hh];
__device__ __align__(16) float g_P[Nn*Hh];
__device__ __align__(16) float g_Q[Nn*Hh];
__device__ __align__(16) float g_vz[Hh];
__device__ __align__(16) float g_czb[Hh];
__device__ int   g_cv[Nn];
__device__ int   g_pidx[Nn*NSLAB*NCAND];
// 3-term split layouts, K=384: A=[hi|lo|hi], B=[hi|hi|lo]
__device__ __align__(16) __nv_bfloat16 g_HtS[Nn*384];
__device__ __align__(16) __nv_bfloat16 g_HsS[Nn*384];

#define SEL_H  0
#define SEL_XW 1
#define SEL_T  2
__device__ __forceinline__ float* buf_ptr(int sel) {
    switch (sel) {
        case SEL_H:  return g_h;
        case SEL_XW: return g_xw;
        default:     return g_t;
    }
}

// ---------------- packed f32x2 helpers ----------------
__device__ __forceinline__ unsigned long long pack2(float x, float y) {
    unsigned long long r;
    asm("mov.b64 %0, {%1, %2};" : "=l"(r) : "f"(x), "f"(y));
    return r;
}
__device__ __forceinline__ float2 unpack2(unsigned long long v) {
    float2 r;
    asm("mov.b64 {%0, %1}, %2;" : "=f"(r.x), "=f"(r.y) : "l"(v));
    return r;
}
__device__ __forceinline__ void fma2(unsigned long long &acc, unsigned long long a2, unsigned long long b2) {
    asm("fma.rn.f32x2 %0, %1, %2, %0;" : "+l"(acc) : "l"(a2), "l"(b2));
}
__device__ __forceinline__ void red4(float* p, float a, float b, float c, float d) {
    asm volatile("red.global.add.v4.f32 [%0], {%1,%2,%3,%4};"
                 :: "l"(p), "f"(a), "f"(b), "f"(c), "f"(d) : "memory");
}
__device__ __forceinline__ uint32_t smem_u32(const void* p) {
    uint32_t a;
    asm("{ .reg .u64 t; cvta.to.shared.u64 t, %1; cvt.u32.u64 %0, t; }" : "=r"(a) : "l"(p));
    return a;
}

// ---------------- scalar GEMM helpers (proven path) ----------------
__device__ __forceinline__ void load_tile_T(const float* __restrict__ G, int row0, int ld,
                                            float* S, int tid) {
#pragma unroll
    for (int i = 0; i < 16; i++) {
        int r  = (tid & 31) + 32*(i >> 2);
        int kq = (tid >> 5) + 8*(i & 3);
        float4 v = *(const float4*)(G + (row0 + r)*ld + kq*4);
        S[(kq*4+0)*PAD + r] = v.x;
        S[(kq*4+1)*PAD + r] = v.y;
        S[(kq*4+2)*PAD + r] = v.z;
        S[(kq*4+3)*PAD + r] = v.w;
    }
}
__device__ __forceinline__ void mm_inner(const float* As, const float* Bs, int ty, int tx,
                                         unsigned long long accp[8][4]) {
#pragma unroll 4
    for (int k = 0; k < 128; k++) {
        const float4 a0 = *(const float4*)&As[k*PAD + ty*8];
        const float4 a1 = *(const float4*)&As[k*PAD + ty*8 + 4];
        const float4 b0 = *(const float4*)&Bs[k*PAD + tx*8];
        const float4 b1 = *(const float4*)&Bs[k*PAD + tx*8 + 4];
        unsigned long long bp[4];
        bp[0] = pack2(b0.x, b0.y); bp[1] = pack2(b0.z, b0.w);
        bp[2] = pack2(b1.x, b1.y); bp[3] = pack2(b1.z, b1.w);
        float av[8] = {a0.x, a0.y, a0.z, a0.w, a1.x, a1.y, a1.z, a1.w};
#pragma unroll
        for (int i = 0; i < 8; i++) {
            unsigned long long ap = pack2(av[i], av[i]);
            fma2(accp[i][0], ap, bp[0]);
            fma2(accp[i][1], ap, bp[1]);
            fma2(accp[i][2], ap, bp[2]);
            fma2(accp[i][3], ap, bp[3]);
        }
    }
}

// ---------------- small kernels ----------------
__global__ void k_deg_init() {
    int i = blockIdx.x*blockDim.x + threadIdx.x;
    if (i < Nn) g_deg[i] = 1.0f;
}
__global__ void k_deg_count(const int* __restrict__ dst) {
    int e = blockIdx.x*blockDim.x + threadIdx.x;
    if (e < Ee) atomicAdd(&g_deg[dst[e]], 1.0f);
}
__global__ void k_rsq() {
    int i = blockIdx.x*blockDim.x + threadIdx.x;
    if (i < Nn) g_rsq[i] = rsqrtf(g_deg[i]);
}
__global__ void k_xw1(const float* __restrict__ x, const float* __restrict__ w) {
    int idx = blockIdx.x*blockDim.x + threadIdx.x;
    if (idx >= Nn*Hh) return;
    int i = idx >> 7, j = idx & 127;
    g_xw[idx] = fmaf(x[2*i], w[2*j], x[2*i+1]*w[2*j+1]);
    g_agg[idx] = 0.0f;
}
__global__ void k_edge_agg(const int* __restrict__ src, const int* __restrict__ dst) {
    int idx = blockIdx.x*blockDim.x + threadIdx.x;
    if (idx >= Ee*32) return;
    int e = idx >> 5, q = idx & 31;
    int s = src[e], d = dst[e];
    float sc = g_rsq[s]*g_rsq[d];
    const float4 v = *(const float4*)(g_xw + s*Hh + q*4);
    red4(g_agg + d*Hh + q*4, sc*v.x, sc*v.y, sc*v.z, sc*v.w);
}
__global__ void k_post(const float* __restrict__ b) {
    int idx = blockIdx.x*blockDim.x + threadIdx.x;
    if (idx >= Nn*Hh) return;
    int i = idx >> 7, j = idx & 127;
    float v = g_agg[idx] + g_xw[idx]/g_deg[i] + b[j];
    g_h[idx] = fmaxf(v, 0.0f);
}
__global__ void k_zvec(const float* __restrict__ np1w, const float* __restrict__ np1b,
                       const float* __restrict__ i1w, const float* __restrict__ i1b,
                       const float* __restrict__ z) {
    int t = threadIdx.x;
    if (t < 128) {
        float s = np1b[t];
        for (int k = 0; k < 128; k++) s = fmaf(np1w[t*256 + 128 + k], z[k], s);
        g_vz[t] = s;
    } else if (t < 256) {
        int j = t - 128;
        float s = i1b[j];
        for (int k = 0; k < 128; k++) s = fmaf(i1w[j*384 + 256 + k], z[k], s);
        g_czb[j] = s;
    }
}
__global__ void k_cv(const int* __restrict__ depth) {
    int v = blockIdx.x*blockDim.x + threadIdx.x;
    if (v >= Nn) return;
    int thr = depth[v] + 1;
    int lo = 0, hi = Nn;
    while (lo < hi) { int mid = (lo + hi) >> 1; if (depth[mid] <= thr) lo = mid + 1; else hi = mid; }
    g_cv[v] = lo;
#pragma unroll
    for (int s = 0; s < NSLAB*NCAND; s++)
        g_pidx[v*NSLAB*NCAND + s] = 0x7fffffff;
}
// split Ht/Hs into 3-term bf16 layouts: A=[hi|lo|hi], B=[hi|hi|lo]
__global__ void k_split() {
    int idx = blockIdx.x*blockDim.x + threadIdx.x;
    if (idx >= Nn*Hh) return;
    int row = idx >> 7, col = idx & 127;
    float a = g_Ht[idx];
    __nv_bfloat16 h = __float2bfloat16(a);
    __nv_bfloat16 l = __float2bfloat16(a - __bfloat162float(h));
    g_HtS[row*384 + col]       = h;
    g_HtS[row*384 + 128 + col] = l;
    g_HtS[row*384 + 256 + col] = h;
    float b = g_Hs[idx];
    __nv_bfloat16 h2 = __float2bfloat16(b);
    __nv_bfloat16 l2 = __float2bfloat16(b - __bfloat162float(h2));
    g_HsS[row*384 + col]       = h2;
    g_HsS[row*384 + 128 + col] = h2;
    g_HsS[row*384 + 256 + col] = l2;
}

// ---------------- fp32 GEMM (scalar path, proven) ----------------
__global__ void __launch_bounds__(256) k_gemm(
    int a_sel, const float* __restrict__ W, int ldw,
    const float* __restrict__ bias, int bias_vz, int c_sel, int relu, int zero_agg)
{
    extern __shared__ float sm[];
    float* As = sm;
    float* Bs = sm + 128*PAD;
    const float* A = buf_ptr(a_sel);
    float* C = buf_ptr(c_sel);
    const float* bptr = bias_vz ? g_vz : bias;
    int tid = threadIdx.x;
    int r0 = blockIdx.x * 128;

    load_tile_T(A, r0, 128, As, tid);
    load_tile_T(W, 0, ldw, Bs, tid);
    __syncthreads();

    int ty = tid >> 4, tx = tid & 15;
    unsigned long long accp[8][4];
#pragma unroll
    for (int i = 0; i < 8; i++)
#pragma unroll
        for (int j = 0; j < 4; j++) accp[i][j] = 0ull;
    mm_inner(As, Bs, ty, tx, accp);

#pragma unroll
    for (int i = 0; i < 8; i++) {
        int r = r0 + ty*8 + i;
        float o[8];
#pragma unroll
        for (int jp = 0; jp < 4; jp++) {
            float2 f = unpack2(accp[i][jp]);
            o[2*jp] = f.x; o[2*jp+1] = f.y;
        }
#pragma unroll
        for (int j = 0; j < 8; j++) {
            if (bptr) o[j] += bptr[tx*8 + j];
            if (relu) o[j] = fmaxf(o[j], 0.0f);
        }
        *(float4*)(C + r*128 + tx*8)     = make_float4(o[0], o[1], o[2], o[3]);
        *(float4*)(C + r*128 + tx*8 + 4) = make_float4(o[4], o[5], o[6], o[7]);
        if (zero_agg) {
            *(float4*)(g_agg + r*128 + tx*8)     = make_float4(0.f, 0.f, 0.f, 0.f);
            *(float4*)(g_agg + r*128 + tx*8 + 4) = make_float4(0.f, 0.f, 0.f, 0.f);
        }
    }
}

// fused 4-way projection: Ht, Hs, P, Q
__global__ void __launch_bounds__(256) k_proj(
    const float* __restrict__ tgtw, const float* __restrict__ srcw,
    const float* __restrict__ i1w)
{
    extern __shared__ float sm[];
    float* As = sm;
    float* Bs = sm + 128*PAD;
    const float* W; int ldw; float* C;
    switch (blockIdx.y) {
        case 0: W = tgtw;       ldw = 128; C = g_Ht; break;
        case 1: W = srcw;       ldw = 128; C = g_Hs; break;
        case 2: W = i1w;        ldw = 384; C = g_P;  break;
        default: W = i1w + 128; ldw = 384; C = g_Q;  break;
    }
    int tid = threadIdx.x;
    int r0 = blockIdx.x * 128;

    load_tile_T(g_h, r0, 128, As, tid);
    load_tile_T(W, 0, ldw, Bs, tid);
    __syncthreads();

    int ty = tid >> 4, tx = tid & 15;
    unsigned long long accp[8][4];
#pragma unroll
    for (int i = 0; i < 8; i++)
#pragma unroll
        for (int j = 0; j < 4; j++) accp[i][j] = 0ull;
    mm_inner(As, Bs, ty, tx, accp);

#pragma unroll
    for (int i = 0; i < 8; i++) {
        int r = r0 + ty*8 + i;
#pragma unroll
        for (int jp = 0; jp < 2; jp++) {
            float2 f0 = unpack2(accp[i][2*jp]);
            float2 f1 = unpack2(accp[i][2*jp+1]);
            *(float4*)(C + r*128 + tx*8 + 4*jp) = make_float4(f0.x, f0.y, f1.x, f1.y);
        }
    }
}

// ---------------- MMA helpers (baseline PTX, sm_80+) ----------------
__device__ __forceinline__ void ldmatrix4(uint32_t &r0, uint32_t &r1, uint32_t &r2, uint32_t &r3,
                                          uint32_t addr) {
    asm volatile("ldmatrix.sync.aligned.m8n8.x4.shared.b16 {%0,%1,%2,%3}, [%4];"
                 : "=r"(r0), "=r"(r1), "=r"(r2), "=r"(r3) : "r"(addr));
}
__device__ __forceinline__ void ldmatrix2(uint32_t &r0, uint32_t &r1, uint32_t addr) {
    asm volatile("ldmatrix.sync.aligned.m8n8.x2.shared.b16 {%0,%1}, [%2];"
                 : "=r"(r0), "=r"(r1) : "r"(addr));
}
__device__ __forceinline__ void mma16816(float &d0, float &d1, float &d2, float &d3,
                                         uint32_t a0, uint32_t a1, uint32_t a2, uint32_t a3,
                                         uint32_t b0, uint32_t b1) {
    asm volatile("mma.sync.aligned.m16n8k16.row.col.f32.bf16.bf16.f32 "
                 "{%0,%1,%2,%3}, {%4,%5,%6,%7}, {%8,%9}, {%0,%1,%2,%3};"
                 : "+f"(d0), "+f"(d1), "+f"(d2), "+f"(d3)
                 : "r"(a0), "r"(a1), "r"(a2), "r"(a3), "r"(b0), "r"(b1));
}
// insert into sorted top-4 list (val desc, tie: lower idx first)
__device__ __forceinline__ void top4ins(float s, int u, float bv[NCAND], int bi[NCAND]) {
    if (!(s > bv[NCAND-1] || (s == bv[NCAND-1] && u < bi[NCAND-1]))) return;
#pragma unroll
    for (int k = 0; k < NCAND; k++) {
        if (s > bv[k] || (s == bv[k] && u < bi[k])) {
#pragma unroll
            for (int m = NCAND-1; m > k; m--) { bv[m] = bv[m-1]; bi[m] = bi[m-1]; }
            bv[k] = s; bi[k] = u;
            return;
        }
    }
}

// ---------------- tensor-core score (mma.sync) + approx top-4 per slab ----------------
// grid (NSLAB, Nn/128), 256 threads = 8 warps. Warp w owns v rows [v0+16w, v0+16w+16).
__global__ void __launch_bounds__(256) k_score_mma()
{
    extern __shared__ char smemc[];
    __nv_bfloat16* As = (__nv_bfloat16*)smemc;            // [128][RS]
    __nv_bfloat16* Bs = As + 128*RS;                      // [128][RS]
    int v0 = blockIdx.y * 128;
    int slab = blockIdx.x;

    int cmax = g_cv[v0 + 127];
    int uend = cmax < 2 ? 2 : cmax;
    if (uend > Nn) uend = Nn;
    int nchunk = (uend + 127) >> 7;
    if (slab >= nchunk) return;

    int tid = threadIdx.x, wid = tid >> 5, lane = tid & 31;
    int lrow = tid >> 1, lpart = tid & 1;   // 2 threads per row for tile loads

    // load A tile: 128 rows x 384 bf16 = 48 uint4/row
#pragma unroll
    for (int i = 0; i < 24; i++) {
        int g = lpart*24 + i;
        *(uint4*)(As + lrow*RS + g*8) = *(const uint4*)(g_HtS + (v0 + lrow)*384 + g*8);
    }
    __syncthreads();

    uint32_t As_b = smem_u32(As);
    uint32_t Bs_b = smem_u32(Bs);
    uint32_t a_addr0 = As_b + ((wid*16 + (lane & 15))*RS + (lane >> 4)*8)*2;
    uint32_t b_addr0 = Bs_b + (((lane & 7))*RS + ((lane >> 3) & 1)*8)*2;

    int row_lo = v0 + wid*16 + (lane >> 2);
    int row_hi = row_lo + 8;
    int cv_lo = g_cv[row_lo], cv_hi = g_cv[row_hi];
    float bvl[NCAND], bvh[NCAND]; int bil[NCAND], bih[NCAND];
#pragma unroll
    for (int k = 0; k < NCAND; k++) {
        bvl[k] = -INFINITY; bvh[k] = -INFINITY; bil[k] = 0x7fffffff; bih[k] = 0x7fffffff;
    }

    for (int c = slab; c < nchunk; c += NSLAB) {
        // load B chunk: rows c*128..+128 x 384 bf16
#pragma unroll
        for (int i = 0; i < 24; i++) {
            int g = lpart*24 + i;
            *(uint4*)(Bs + lrow*RS + g*8) = *(const uint4*)(g_HsS + (c*128 + lrow)*384 + g*8);
        }
        __syncthreads();

        float d[16][4];
#pragma unroll
        for (int nb = 0; nb < 16; nb++)
#pragma unroll
            for (int j = 0; j < 4; j++) d[nb][j] = 0.0f;

#pragma unroll 2
        for (int ks = 0; ks < KS_N; ks++) {
            uint32_t a0, a1, a2, a3;
            ldmatrix4(a0, a1, a2, a3, a_addr0 + ks*32);
#pragma unroll
            for (int nb = 0; nb < 16; nb++) {
                uint32_t bb0, bb1;
                ldmatrix2(bb0, bb1, b_addr0 + (nb*8*RS)*2 + ks*32);
                mma16816(d[nb][0], d[nb][1], d[nb][2], d[nb][3], a0, a1, a2, a3, bb0, bb1);
            }
        }

        // top-4 update (approx values; tie lower index)
        int ubase = c*128 + 2*(lane & 3);
#pragma unroll
        for (int nb = 0; nb < 16; nb++) {
            int u0 = ubase + nb*8, u1 = u0 + 1;
            top4ins(u0 < cv_lo ? d[nb][0] : NEGV, u0, bvl, bil);
            top4ins(u1 < cv_lo ? d[nb][1] : NEGV, u1, bvl, bil);
            top4ins(u0 < cv_hi ? d[nb][2] : NEGV, u0, bvh, bih);
            top4ins(u1 < cv_hi ? d[nb][3] : NEGV, u1, bvh, bih);
        }
        __syncthreads();    // B smem reused next chunk
    }

    // reduce across the 4 lanes of each row group (xor 1, 2)
#pragma unroll
    for (int off = 1; off <= 2; off <<= 1) {
#pragma unroll
        for (int k = 0; k < NCAND; k++) {
            float ov = __shfl_xor_sync(0xffffffffu, bvl[k], off);
            int   oi = __shfl_xor_sync(0xffffffffu, bil[k], off);
            top4ins(ov, oi, bvl, bil);
        }
#pragma unroll
        for (int k = 0; k < NCAND; k++) {
            float ov = __shfl_xor_sync(0xffffffffu, bvh[k], off);
            int   oi = __shfl_xor_sync(0xffffffffu, bih[k], off);
            top4ins(ov, oi, bvh, bih);
        }
    }
    if ((lane & 3) == 0) {
        int o = (row_lo*NSLAB + slab)*NCAND;
#pragma unroll
        for (int k = 0; k < NCAND; k++) g_pidx[o + k] = bil[k];
        o = (row_hi*NSLAB + slab)*NCAND;
#pragma unroll
        for (int k = 0; k < NCAND; k++) g_pidx[o + k] = bih[k];
    }
}

// ---------------- merge: exact fp32 rescore of 32 candidates + inv-MLP + valid ----------------
__global__ void k_mergefinal(const float* __restrict__ w2, const float* __restrict__ b2,
                             const float* __restrict__ x, const int* __restrict__ depth,
                             float* __restrict__ out)
{
    int v = blockIdx.x;
    int tid = threadIdx.x;          // 128 threads
    int wid = tid >> 5, lane = tid & 31;
    __shared__ float sHt[128];
    __shared__ float cval[NSLAB*NCAND];
    __shared__ int   cidx[NSLAB*NCAND];
    __shared__ int su[2];
    __shared__ float wsum[2][4];

    sHt[tid] = g_Ht[v*128 + tid];
    if (tid < NSLAB*NCAND) cidx[tid] = g_pidx[v*NSLAB*NCAND + tid];
    __syncthreads();

    // exact rescore: warp w handles candidates 8w..8w+7
    float4 ht = *(const float4*)(&sHt[lane*4]);
#pragma unroll
    for (int q = 0; q < 8; q++) {
        int ci = wid*8 + q;
        int u = cidx[ci];
        float s = -INFINITY;
        if (u < Nn) {
            float4 hs = *(const float4*)(g_Hs + u*128 + lane*4);
            float p = ht.x*hs.x;
            p = fmaf(ht.y, hs.y, p);
            p = fmaf(ht.z, hs.z, p);
            p = fmaf(ht.w, hs.w, p);
#pragma unroll
            for (int off = 16; off > 0; off >>= 1)
                p += __shfl_xor_sync(0xffffffffu, p, off);
            s = (u < g_cv[v]) ? p : NEGV;
        }
        if (lane == 0) cval[ci] = s;
    }
    __syncthreads();

    if (tid == 0) {
        float a1 = -INFINITY, a2 = -INFINITY; int ai1 = 0x7fffffff, ai2 = 0x7fffffff;
#pragma unroll
        for (int s = 0; s < NSLAB*NCAND; s++) {
            float c1 = cval[s]; int ci1 = cidx[s];
            if (c1 > a1 || (c1 == a1 && ci1 < ai1)) {
                a2 = a1; ai2 = ai1; a1 = c1; ai1 = ci1;
            } else if (c1 > a2 || (c1 == a2 && ci1 < ai2)) {
                a2 = c1; ai2 = ci1;
            }
        }
        out[v*2 + 0] = a1;
        out[v*2 + 1] = a2;
        out[4*Nn + v*2 + 0] = (float)ai1;
        out[4*Nn + v*2 + 1] = (float)ai2;
        su[0] = (ai1 >= 0 && ai1 < Nn) ? ai1 : 0;
        su[1] = (ai2 >= 0 && ai2 < Nn) ? ai2 : 0;
    }
    __syncthreads();

    int j = tid;
#pragma unroll
    for (int k = 0; k < 2; k++) {
        int u = su[k];
        float t = g_P[u*Hh + j] + g_Q[v*Hh + j] + g_czb[j];
        t = fmaxf(t, 0.0f);
        float p = t * w2[j];
#pragma unroll
        for (int off = 16; off > 0; off >>= 1)
            p += __shfl_xor_sync(0xffffffffu, p, off);
        if ((j & 31) == 0) wsum[k][j >> 5] = p;
    }
    __syncthreads();
    if (j < 2) {
        float lg = wsum[j][0] + wsum[j][1] + wsum[j][2] + wsum[j][3] + b2[0];
        out[2*Nn + v*2 + j] = lg;
        out[6*Nn + v*2 + j] = (lg > 0.0f) ? 1.0f : 0.0f;
    } else if (j == 2) {
        int tpy = (int)x[v*2];
        int c = g_cv[v];
        bool tv = (depth[v] >= 1) && (tpy != 0);
        out[8*Nn + v*2 + 0] = (tv && c >= 1) ? 1.0f : 0.0f;
        out[8*Nn + v*2 + 1] = (tv && tpy == 2 && c >= 2) ? 1.0f : 0.0f;
    }
}

// ---------------- launch ----------------
extern "C" void kernel_launch(void* const* d_in, const int* in_sizes, int n_in,
                              void* d_out, int out_size)
{
    const float* x     = (const float*)d_in[0];
    const float* z     = (const float*)d_in[1];
    const int*   ei    = (const int*)  d_in[2];
    const int*   depth = (const int*)  d_in[3];
    const float* c1w = (const float*)d_in[4];
    const float* c1b = (const float*)d_in[5];
    const float* c2w = (const float*)d_in[6];
    const float* c2b = (const float*)d_in[7];
    const float* np1w = (const float*)d_in[8];
    const float* np1b = (const float*)d_in[9];
    const float* np2w = (const float*)d_in[10];
    const float* np2b = (const float*)d_in[11];
    const float* srcw = (const float*)d_in[12];
    const float* tgtw = (const float*)d_in[13];
    const float* i1w  = (const float*)d_in[14];
    const float* i1b  = (const float*)d_in[15];
    const float* i2w  = (const float*)d_in[16];
    const float* i2b  = (const float*)d_in[17];
    const int* esrc = ei;
    const int* edst = ei + Ee;
    float* out = (float*)d_out;

    cudaFuncSetAttribute(k_gemm,      cudaFuncAttributeMaxDynamicSharedMemorySize, SMEM_GEMM);
    cudaFuncSetAttribute(k_proj,      cudaFuncAttributeMaxDynamicSharedMemorySize, SMEM_GEMM);
    cudaFuncSetAttribute(k_score_mma, cudaFuncAttributeMaxDynamicSharedMemorySize, SMEM_MMA);

    const int NB = 256;
    k_deg_init <<<Nn/NB, NB>>>();
    k_deg_count<<<Ee/NB, NB>>>(edst);
    k_rsq      <<<Nn/NB, NB>>>();
    // GCN layer 1
    k_xw1      <<<(Nn*Hh)/NB, NB>>>(x, c1w);
    k_edge_agg <<<(Ee*32)/NB, NB>>>(esrc, edst);
    k_post     <<<(Nn*Hh)/NB, NB>>>(c1b);
    // GCN layer 2
    k_gemm<<<Nn/128, NB, SMEM_GEMM>>>(SEL_H, c2w, 128, nullptr, 0, SEL_XW, 0, 1);
    k_edge_agg <<<(Ee*32)/NB, NB>>>(esrc, edst);
    k_post     <<<(Nn*Hh)/NB, NB>>>(c2b);
    // z-dependent constants
    k_zvec<<<1, 256>>>(np1w, np1b, i1w, i1b, z);
    // node_proj
    k_gemm<<<Nn/128, NB, SMEM_GEMM>>>(SEL_H, np1w, 256, nullptr, 1, SEL_T, 1, 0);
    k_gemm<<<Nn/128, NB, SMEM_GEMM>>>(SEL_T, np2w, 128, np2b,    0, SEL_H, 0, 0);
    // projections (Ht, Hs, P, Q)
    dim3 pgrid(Nn/128, 4);
    k_proj<<<pgrid, NB, SMEM_GEMM>>>(tgtw, srcw, i1w);
    // 3-term bf16 split of Ht/Hs
    k_split<<<(Nn*Hh)/NB, NB>>>();
    // candidate counts (+ cand init), MMA score, exact merge
    k_cv<<<Nn/NB, NB>>>(depth);
    dim3 sgrid(NSLAB, Nn/128);
    k_score_mma<<<sgrid, NB, SMEM_MMA>>>();
    k_mergefinal<<<Nn, 128>>>(i2w, i2b, x, depth, out);
    (void)in_sizes; (void)n_in; (void)out_size;
}

// round 12
// speedup vs baseline: 1.4671x; 1.4671x over previous
#include <cuda_runtime.h>
#include <math.h>
#include <stdint.h>

#define Nn 8192
#define Ee 131072
#define Hh 128
#define NEGV (-1e30f)
#define NSLAB 16
#define PAD 132
#define SMEM_GEMM  (2*128*PAD*4)     // 135 KB: As + Bs
#define SMEM_SCORE (3*128*PAD*4)     // 203 KB: As + 2x Bs (double buffer)

// ---------------- device scratch (no allocations allowed) ----------------
__device__ __align__(16) float g_deg[Nn];
__device__ __align__(16) float g_rsq[Nn];
__device__ __align__(16) float g_xw[Nn*Hh];
__device__ __align__(16) float g_agg[Nn*Hh];
__device__ __align__(16) float g_h[Nn*Hh];
__device__ __align__(16) float g_t[Nn*Hh];
__device__ __align__(16) float g_Ht[Nn*Hh];
__device__ __align__(16) float g_Hs[Nn*Hh];
__device__ __align__(16) float g_P[Nn*Hh];
__device__ __align__(16) float g_Q[Nn*Hh];
__device__ __align__(16) float g_vz[Hh];
__device__ __align__(16) float g_czb[Hh];
__device__ int   g_cv[Nn];
__device__ __align__(16) float g_pval[Nn*NSLAB*2];
__device__ int   g_pidx[Nn*NSLAB*2];

#define SEL_H  0
#define SEL_XW 1
#define SEL_T  2
__device__ __forceinline__ float* buf_ptr(int sel) {
    switch (sel) {
        case SEL_H:  return g_h;
        case SEL_XW: return g_xw;
        default:     return g_t;
    }
}

// ---------------- packed f32x2 helpers ----------------
__device__ __forceinline__ unsigned long long pack2(float x, float y) {
    unsigned long long r;
    asm("mov.b64 %0, {%1, %2};" : "=l"(r) : "f"(x), "f"(y));
    return r;
}
__device__ __forceinline__ float2 unpack2(unsigned long long v) {
    float2 r;
    asm("mov.b64 {%0, %1}, %2;" : "=f"(r.x), "=f"(r.y) : "l"(v));
    return r;
}
__device__ __forceinline__ void fma2(unsigned long long &acc, unsigned long long a2, unsigned long long b2) {
    asm("fma.rn.f32x2 %0, %1, %2, %0;" : "+l"(acc) : "l"(a2), "l"(b2));
}
__device__ __forceinline__ void red4(float* p, float a, float b, float c, float d) {
    asm volatile("red.global.add.v4.f32 [%0], {%1,%2,%3,%4};"
                 :: "l"(p), "f"(a), "f"(b), "f"(c), "f"(d) : "memory");
}

// Conflict-free k-major transpose load: G rows [row0,row0+128) x 128 cols (stride ld) -> S[k][r]
__device__ __forceinline__ void load_tile_T(const float* __restrict__ G, int row0, int ld,
                                            float* S, int tid) {
#pragma unroll
    for (int i = 0; i < 16; i++) {
        int r  = (tid & 31) + 32*(i >> 2);
        int kq = (tid >> 5) + 8*(i & 3);
        float4 v = *(const float4*)(G + (row0 + r)*ld + kq*4);
        S[(kq*4+0)*PAD + r] = v.x;
        S[(kq*4+1)*PAD + r] = v.y;
        S[(kq*4+2)*PAD + r] = v.z;
        S[(kq*4+3)*PAD + r] = v.w;
    }
}

// 8x8 microtile inner product over K=128, packed f32x2 accumulators [8 rows][4 col-pairs]
// B pairs loaded directly as 64-bit values (16B-aligned: PAD*4=528 = 16*33, tx*8*4=32B steps)
__device__ __forceinline__ void mm_inner(const float* As, const float* Bs, int ty, int tx,
                                         unsigned long long accp[8][4]) {
#pragma unroll 4
    for (int k = 0; k < 128; k++) {
        const float4 a0 = *(const float4*)&As[k*PAD + ty*8];
        const float4 a1 = *(const float4*)&As[k*PAD + ty*8 + 4];
        const unsigned long long* bq = (const unsigned long long*)&Bs[k*PAD + tx*8];
        unsigned long long bp[4];
        bp[0] = bq[0]; bp[1] = bq[1]; bp[2] = bq[2]; bp[3] = bq[3];
        float av[8] = {a0.x, a0.y, a0.z, a0.w, a1.x, a1.y, a1.z, a1.w};
#pragma unroll
        for (int i = 0; i < 8; i++) {
            unsigned long long ap = pack2(av[i], av[i]);
            fma2(accp[i][0], ap, bp[0]);
            fma2(accp[i][1], ap, bp[1]);
            fma2(accp[i][2], ap, bp[2]);
            fma2(accp[i][3], ap, bp[3]);
        }
    }
}

// ---------------- small kernels ----------------
__global__ void k_deg_init() {
    int i = blockIdx.x*blockDim.x + threadIdx.x;
    if (i < Nn) g_deg[i] = 1.0f;
}
__global__ void k_deg_count(const int* __restrict__ dst) {
    int e = blockIdx.x*blockDim.x + threadIdx.x;
    if (e < Ee) atomicAdd(&g_deg[dst[e]], 1.0f);
}
__global__ void k_rsq() {
    int i = blockIdx.x*blockDim.x + threadIdx.x;
    if (i < Nn) g_rsq[i] = rsqrtf(g_deg[i]);
}
__global__ void k_xw1(const float* __restrict__ x, const float* __restrict__ w) {
    int idx = blockIdx.x*blockDim.x + threadIdx.x;
    if (idx >= Nn*Hh) return;
    int i = idx >> 7, j = idx & 127;
    g_xw[idx] = fmaf(x[2*i], w[2*j], x[2*i+1]*w[2*j+1]);
    g_agg[idx] = 0.0f;
}
__global__ void k_edge_agg(const int* __restrict__ src, const int* __restrict__ dst) {
    int idx = blockIdx.x*blockDim.x + threadIdx.x;
    if (idx >= Ee*32) return;
    int e = idx >> 5, q = idx & 31;
    int s = src[e], d = dst[e];
    float sc = g_rsq[s]*g_rsq[d];
    const float4 v = *(const float4*)(g_xw + s*Hh + q*4);
    red4(g_agg + d*Hh + q*4, sc*v.x, sc*v.y, sc*v.z, sc*v.w);
}
__global__ void k_post(const float* __restrict__ b) {
    int idx = blockIdx.x*blockDim.x + threadIdx.x;
    if (idx >= Nn*Hh) return;
    int i = idx >> 7, j = idx & 127;
    float v = g_agg[idx] + g_xw[idx]/g_deg[i] + b[j];
    g_h[idx] = fmaxf(v, 0.0f);
}
__global__ void k_zvec(const float* __restrict__ np1w, const float* __restrict__ np1b,
                       const float* __restrict__ i1w, const float* __restrict__ i1b,
                       const float* __restrict__ z) {
    int t = threadIdx.x;
    if (t < 128) {
        float s = np1b[t];
        for (int k = 0; k < 128; k++) s = fmaf(np1w[t*256 + 128 + k], z[k], s);
        g_vz[t] = s;
    } else if (t < 256) {
        int j = t - 128;
        float s = i1b[j];
        for (int k = 0; k < 128; k++) s = fmaf(i1w[j*384 + 256 + k], z[k], s);
        g_czb[j] = s;
    }
}
// candidate counts + partial-top2 init (fused)
__global__ void k_cv(const int* __restrict__ depth) {
    int v = blockIdx.x*blockDim.x + threadIdx.x;
    if (v >= Nn) return;
    int thr = depth[v] + 1;
    int lo = 0, hi = Nn;
    while (lo < hi) { int mid = (lo + hi) >> 1; if (depth[mid] <= thr) lo = mid + 1; else hi = mid; }
    g_cv[v] = lo;
#pragma unroll
    for (int s = 0; s < NSLAB*2; s++) {
        g_pval[v*NSLAB*2 + s] = -INFINITY;
        g_pidx[v*NSLAB*2 + s] = 0x7fffffff;
    }
}

// ---------------- fp32 GEMM: C[8192 x 128] = A @ W^T (+bias, relu) ----------------
__global__ void __launch_bounds__(256) k_gemm(
    int a_sel, const float* __restrict__ W, int ldw,
    const float* __restrict__ bias, int bias_vz, int c_sel, int relu, int zero_agg)
{
    extern __shared__ float sm[];
    float* As = sm;
    float* Bs = sm + 128*PAD;
    const float* A = buf_ptr(a_sel);
    float* C = buf_ptr(c_sel);
    const float* bptr = bias_vz ? g_vz : bias;
    int tid = threadIdx.x;
    int r0 = blockIdx.x * 128;

    load_tile_T(A, r0, 128, As, tid);
    load_tile_T(W, 0, ldw, Bs, tid);
    __syncthreads();

    int ty = tid >> 4, tx = tid & 15;
    unsigned long long accp[8][4];
#pragma unroll
    for (int i = 0; i < 8; i++)
#pragma unroll
        for (int j = 0; j < 4; j++) accp[i][j] = 0ull;
    mm_inner(As, Bs, ty, tx, accp);

#pragma unroll
    for (int i = 0; i < 8; i++) {
        int r = r0 + ty*8 + i;
        float o[8];
#pragma unroll
        for (int jp = 0; jp < 4; jp++) {
            float2 f = unpack2(accp[i][jp]);
            o[2*jp] = f.x; o[2*jp+1] = f.y;
        }
#pragma unroll
        for (int j = 0; j < 8; j++) {
            if (bptr) o[j] += bptr[tx*8 + j];
            if (relu) o[j] = fmaxf(o[j], 0.0f);
        }
        *(float4*)(C + r*128 + tx*8)     = make_float4(o[0], o[1], o[2], o[3]);
        *(float4*)(C + r*128 + tx*8 + 4) = make_float4(o[4], o[5], o[6], o[7]);
        if (zero_agg) {
            *(float4*)(g_agg + r*128 + tx*8)     = make_float4(0.f, 0.f, 0.f, 0.f);
            *(float4*)(g_agg + r*128 + tx*8 + 4) = make_float4(0.f, 0.f, 0.f, 0.f);
        }
    }
}

// fused 4-way projection: blockIdx.y selects (W, ld, C): Ht, Hs, P, Q
__global__ void __launch_bounds__(256) k_proj(
    const float* __restrict__ tgtw, const float* __restrict__ srcw,
    const float* __restrict__ i1w)
{
    extern __shared__ float sm[];
    float* As = sm;
    float* Bs = sm + 128*PAD;
    const float* W; int ldw; float* C;
    switch (blockIdx.y) {
        case 0: W = tgtw;       ldw = 128; C = g_Ht; break;
        case 1: W = srcw;       ldw = 128; C = g_Hs; break;
        case 2: W = i1w;        ldw = 384; C = g_P;  break;
        default: W = i1w + 128; ldw = 384; C = g_Q;  break;
    }
    int tid = threadIdx.x;
    int r0 = blockIdx.x * 128;

    load_tile_T(g_h, r0, 128, As, tid);
    load_tile_T(W, 0, ldw, Bs, tid);
    __syncthreads();

    int ty = tid >> 4, tx = tid & 15;
    unsigned long long accp[8][4];
#pragma unroll
    for (int i = 0; i < 8; i++)
#pragma unroll
        for (int j = 0; j < 4; j++) accp[i][j] = 0ull;
    mm_inner(As, Bs, ty, tx, accp);

#pragma unroll
    for (int i = 0; i < 8; i++) {
        int r = r0 + ty*8 + i;
#pragma unroll
        for (int jp = 0; jp < 2; jp++) {
            float2 f0 = unpack2(accp[i][2*jp]);
            float2 f1 = unpack2(accp[i][2*jp+1]);
            *(float4*)(C + r*128 + tx*8 + 4*jp) = make_float4(f0.x, f0.y, f1.x, f1.y);
        }
    }
}

// ---------------- fused score GEMM + masked top-2 (double-buffered Bs, heavy-first) ----------------
// grid (NSLAB, Nn/128). Heavy tiles (large cv) scheduled first via reversed blockIdx.y map.
__global__ void __launch_bounds__(256) k_score()
{
    extern __shared__ float sm[];
    float* As = sm;
    float* Bsb[2] = { sm + 128*PAD, sm + 2*128*PAD };
    int v0 = (gridDim.y - 1 - blockIdx.y) * 128;    // heavy-first (cv non-decreasing in v)
    int slab = blockIdx.x;

    int cmax = g_cv[v0 + 127];          // c_v non-decreasing (depth sorted)
    int uend = cmax < 2 ? 2 : cmax;     // >=2 so masked NEG idx ties match top_k
    if (uend > Nn) uend = Nn;
    int nchunk = (uend + 127) >> 7;
    if (slab >= nchunk) return;

    int tid = threadIdx.x;
    load_tile_T(g_Ht, v0, 128, As, tid);

    int ty = tid >> 4, tx = tid & 15;
    int cvr[8]; float b1[8], b2[8]; int i1[8], i2[8];
#pragma unroll
    for (int i = 0; i < 8; i++) {
        cvr[i] = g_cv[v0 + ty*8 + i];
        b1[i] = -INFINITY; b2[i] = -INFINITY; i1[i] = 0x7fffffff; i2[i] = 0x7fffffff;
    }

    // per-thread lane mapping (matches load_tile_T)
    int pr[16], pk[16];
#pragma unroll
    for (int i = 0; i < 16; i++) {
        pr[i] = (tid & 31) + 32*(i >> 2);
        pk[i] = (tid >> 5) + 8*(i & 3);
    }

    // prologue: fetch chunk 'slab' into buf 0
    float4 pf[16];
    int c = slab;
#pragma unroll
    for (int i = 0; i < 16; i++)
        pf[i] = *(const float4*)(g_Hs + (c*128 + pr[i])*128 + pk[i]*4);
    {
        float* B = Bsb[0];
#pragma unroll
        for (int i = 0; i < 16; i++) {
            B[(pk[i]*4+0)*PAD + pr[i]] = pf[i].x;
            B[(pk[i]*4+1)*PAD + pr[i]] = pf[i].y;
            B[(pk[i]*4+2)*PAD + pr[i]] = pf[i].z;
            B[(pk[i]*4+3)*PAD + pr[i]] = pf[i].w;
        }
    }
    __syncthreads();

    int buf = 0;
    while (c < nchunk) {
        int cn = c + NSLAB;
        if (cn < nchunk) {
#pragma unroll
            for (int i = 0; i < 16; i++)
                pf[i] = *(const float4*)(g_Hs + (cn*128 + pr[i])*128 + pk[i]*4);
        }

        unsigned long long accp[8][4];
#pragma unroll
        for (int i = 0; i < 8; i++)
#pragma unroll
            for (int j = 0; j < 4; j++) accp[i][j] = 0ull;
        mm_inner(As, Bsb[buf], ty, tx, accp);

        if (cn < nchunk) {
            float* B = Bsb[buf^1];
#pragma unroll
            for (int i = 0; i < 16; i++) {
                B[(pk[i]*4+0)*PAD + pr[i]] = pf[i].x;
                B[(pk[i]*4+1)*PAD + pr[i]] = pf[i].y;
                B[(pk[i]*4+2)*PAD + pr[i]] = pf[i].z;
                B[(pk[i]*4+3)*PAD + pr[i]] = pf[i].w;
            }
        }

        // top-2 update for this chunk (tie: lower index wins, matching lax.top_k)
        int ub = c*128;
#pragma unroll
        for (int i = 0; i < 8; i++) {
#pragma unroll
            for (int jp = 0; jp < 4; jp++) {
                float2 f = unpack2(accp[i][jp]);
                float sv[2] = {f.x, f.y};
#pragma unroll
                for (int h = 0; h < 2; h++) {
                    int u = ub + tx*8 + 2*jp + h;
                    float s = (u < cvr[i]) ? sv[h] : NEGV;
                    if (s > b1[i] || (s == b1[i] && u < i1[i])) {
                        b2[i] = b1[i]; i2[i] = i1[i]; b1[i] = s; i1[i] = u;
                    } else if (s > b2[i] || (s == b2[i] && u < i2[i])) {
                        b2[i] = s; i2[i] = u;
                    }
                }
            }
        }
        __syncthreads();
        buf ^= 1;
        c = cn;
    }

    // reduce across the 16 tx lanes
#pragma unroll
    for (int off = 1; off < 16; off <<= 1) {
#pragma unroll
        for (int i = 0; i < 8; i++) {
            float ob1 = __shfl_xor_sync(0xffffffffu, b1[i], off);
            int   oi1 = __shfl_xor_sync(0xffffffffu, i1[i], off);
            float ob2 = __shfl_xor_sync(0xffffffffu, b2[i], off);
            int   oi2 = __shfl_xor_sync(0xffffffffu, i2[i], off);
            if (ob1 > b1[i] || (ob1 == b1[i] && oi1 < i1[i])) {
                float n2; int n2i;
                if (b1[i] > ob2 || (b1[i] == ob2 && i1[i] < oi2)) { n2 = b1[i]; n2i = i1[i]; }
                else { n2 = ob2; n2i = oi2; }
                b1[i] = ob1; i1[i] = oi1; b2[i] = n2; i2[i] = n2i;
            } else if (ob1 > b2[i] || (ob1 == b2[i] && oi1 < i2[i])) {
                b2[i] = ob1; i2[i] = oi1;
            }
        }
    }
    if (tx == 0) {
#pragma unroll
        for (int i = 0; i < 8; i++) {
            int v = v0 + ty*8 + i;
            int o = (v*NSLAB + slab)*2;
            g_pval[o]   = b1[i]; g_pidx[o]   = i1[i];
            g_pval[o+1] = b2[i]; g_pidx[o+1] = i2[i];
        }
    }
}

// ---------------- fused merge + inversion-bit MLP + valid flags ----------------
__global__ void k_mergefinal(const float* __restrict__ w2, const float* __restrict__ b2,
                             const float* __restrict__ x, const int* __restrict__ depth,
                             float* __restrict__ out)
{
    int v = blockIdx.x;
    int j = threadIdx.x;            // 128 threads
    __shared__ int su[2];
    __shared__ float wsum[2][4];

    if (j == 0) {
        float a1 = -INFINITY, a2 = -INFINITY; int ai1 = 0x7fffffff, ai2 = 0x7fffffff;
#pragma unroll
        for (int s = 0; s < NSLAB; s++) {
            int o = (v*NSLAB + s)*2;
            float c1 = g_pval[o]; int ci1 = g_pidx[o];
            float c2 = g_pval[o+1]; int ci2 = g_pidx[o+1];
            if (c1 > a1 || (c1 == a1 && ci1 < ai1)) {
                float n2; int n2i;
                if (a1 > c2 || (a1 == c2 && ai1 < ci2)) { n2 = a1; n2i = ai1; }
                else { n2 = c2; n2i = ci2; }
                a1 = c1; ai1 = ci1; a2 = n2; ai2 = n2i;
            } else if (c1 > a2 || (c1 == a2 && ci1 < ai2)) {
                a2 = c1; ai2 = ci1;
            }
        }
        out[v*2 + 0] = a1;
        out[v*2 + 1] = a2;
        out[4*Nn + v*2 + 0] = (float)ai1;
        out[4*Nn + v*2 + 1] = (float)ai2;
        su[0] = (ai1 >= 0 && ai1 < Nn) ? ai1 : 0;
        su[1] = (ai2 >= 0 && ai2 < Nn) ? ai2 : 0;
    }
    __syncthreads();

#pragma unroll
    for (int k = 0; k < 2; k++) {
        int u = su[k];
        float t = g_P[u*Hh + j] + g_Q[v*Hh + j] + g_czb[j];
        t = fmaxf(t, 0.0f);
        float p = t * w2[j];
#pragma unroll
        for (int off = 16; off > 0; off >>= 1)
            p += __shfl_xor_sync(0xffffffffu, p, off);
        if ((j & 31) == 0) wsum[k][j >> 5] = p;
    }
    __syncthreads();
    if (j < 2) {
        float lg = wsum[j][0] + wsum[j][1] + wsum[j][2] + wsum[j][3] + b2[0];
        out[2*Nn + v*2 + j] = lg;
        out[6*Nn + v*2 + j] = (lg > 0.0f) ? 1.0f : 0.0f;
    } else if (j == 2) {
        int tpy = (int)x[v*2];
        int c = g_cv[v];
        bool tv = (depth[v] >= 1) && (tpy != 0);
        out[8*Nn + v*2 + 0] = (tv && c >= 1) ? 1.0f : 0.0f;
        out[8*Nn + v*2 + 1] = (tv && tpy == 2 && c >= 2) ? 1.0f : 0.0f;
    }
}

// ---------------- launch ----------------
extern "C" void kernel_launch(void* const* d_in, const int* in_sizes, int n_in,
                              void* d_out, int out_size)
{
    const float* x     = (const float*)d_in[0];
    const float* z     = (const float*)d_in[1];
    const int*   ei    = (const int*)  d_in[2];
    const int*   depth = (const int*)  d_in[3];
    const float* c1w = (const float*)d_in[4];
    const float* c1b = (const float*)d_in[5];
    const float* c2w = (const float*)d_in[6];
    const float* c2b = (const float*)d_in[7];
    const float* np1w = (const float*)d_in[8];
    const float* np1b = (const float*)d_in[9];
    const float* np2w = (const float*)d_in[10];
    const float* np2b = (const float*)d_in[11];
    const float* srcw = (const float*)d_in[12];
    const float* tgtw = (const float*)d_in[13];
    const float* i1w  = (const float*)d_in[14];
    const float* i1b  = (const float*)d_in[15];
    const float* i2w  = (const float*)d_in[16];
    const float* i2b  = (const float*)d_in[17];
    const int* esrc = ei;
    const int* edst = ei + Ee;
    float* out = (float*)d_out;

    cudaFuncSetAttribute(k_gemm,  cudaFuncAttributeMaxDynamicSharedMemorySize, SMEM_GEMM);
    cudaFuncSetAttribute(k_proj,  cudaFuncAttributeMaxDynamicSharedMemorySize, SMEM_GEMM);
    cudaFuncSetAttribute(k_score, cudaFuncAttributeMaxDynamicSharedMemorySize, SMEM_SCORE);

    const int NB = 256;
    k_deg_init <<<Nn/NB, NB>>>();
    k_deg_count<<<Ee/NB, NB>>>(edst);
    k_rsq      <<<Nn/NB, NB>>>();
    // GCN layer 1 (xw + zero agg fused)
    k_xw1      <<<(Nn*Hh)/NB, NB>>>(x, c1w);
    k_edge_agg <<<(Ee*32)/NB, NB>>>(esrc, edst);
    k_post     <<<(Nn*Hh)/NB, NB>>>(c1b);
    // GCN layer 2 (gemm epilogue zeroes g_agg)
    k_gemm<<<Nn/128, NB, SMEM_GEMM>>>(SEL_H, c2w, 128, nullptr, 0, SEL_XW, 0, 1);
    k_edge_agg <<<(Ee*32)/NB, NB>>>(esrc, edst);
    k_post     <<<(Nn*Hh)/NB, NB>>>(c2b);
    // z-dependent constant vectors
    k_zvec<<<1, 256>>>(np1w, np1b, i1w, i1b, z);
    // node_proj
    k_gemm<<<Nn/128, NB, SMEM_GEMM>>>(SEL_H, np1w, 256, nullptr, 1, SEL_T, 1, 0);
    k_gemm<<<Nn/128, NB, SMEM_GEMM>>>(SEL_T, np2w, 128, np2b,    0, SEL_H, 0, 0);
    // fused projections (Ht, Hs, P, Q)
    dim3 pgrid(Nn/128, 4);
    k_proj<<<pgrid, NB, SMEM_GEMM>>>(tgtw, srcw, i1w);
    // candidate counts (+ partial init) and fused score/top-2
    k_cv<<<Nn/NB, NB>>>(depth);
    dim3 sgrid(NSLAB, Nn/128);
    k_score<<<sgrid, NB, SMEM_SCORE>>>();
    // merge + inv-MLP + valid
    k_mergefinal<<<Nn, 128>>>(i2w, i2b, x, depth, out);
    (void)in_sizes; (void)n_in; (void)out_size;
}